// round 15
// baseline (speedup 1.0000x reference)
#include <cuda_runtime.h>
#include <cuda_bf16.h>
#include <cuda_fp16.h>
#include <mma.h>
#include <cstdint>
#include <cstddef>

using namespace nvcuda;

#define NN 200000
#define EE 3200000
#define GG 2000
#define NBLK 196   // ceil(NN/1024)
#define WSZ (5 * 49152 + 24576)  // total W^T elements across 6 layers

// ---------------- device scratch (static, allocation-free) ----------------
__device__ int   g_cnt[NN];
__device__ int   g_off[NN + 1];
__device__ int   g_cursor[NN];
__device__ int   g_bsums[NBLK];
__device__ int   g_bscan[NBLK];
__device__ int   g_csr_src[EE];
__device__ float g_csr_norm[EE];
__device__ float g_norm[NN];
__device__ __half g_h16[(size_t)NN * 128];  // fp16 copy of current h (gather input)
__device__ __half g_p1h[(size_t)NN * 128];  // fp16 prop1
__device__ __half g_p2h[(size_t)NN * 128];  // fp16 prop2
__device__ float g_y [(size_t)NN * 128];    // GEMM output
__device__ float g_o0[(size_t)NN * 128];    // rotating layer outputs
__device__ float g_o1[(size_t)NN * 128];
__device__ float g_o2[(size_t)NN * 128];
__device__ __nv_bfloat16 g_bh[WSZ];         // W^T bf16 hi, all layers [l][n][k]
__device__ __nv_bfloat16 g_bl[WSZ];         // W^T bf16 lo
__device__ float g_stats[256];
__device__ int   g_starts[GG + 1];
__device__ float g_pool[(size_t)GG * 4 * 64];
__device__ float g_aggstats[8];
__device__ int   g_flags[2];

// ---------------- misc helpers ----------------
__device__ __forceinline__ int load_idx(const void* p, long long i, int is64) {
    if (is64) return (int)((const long long*)p)[i];
    return ((const int*)p)[i];
}

__global__ void detect_kernel(const unsigned* e, const unsigned* s) {
    if (threadIdx.x == 0 && blockIdx.x == 0) {
        int z = 1;
        for (int i = 1; i < 128; i += 2) if (e[i] != 0) { z = 0; break; }
        g_flags[0] = z;
        z = 1;
        for (int i = NN - 127; i < NN; i += 2) if (s[i] != 0) { z = 0; break; }
        g_flags[1] = z;
    }
}

__global__ void zero_kernel(float* p, long long n) {
    long long i = (long long)blockIdx.x * blockDim.x + threadIdx.x;
    long long i4 = i * 4;
    if (i4 + 3 < n) {
        *(float4*)(p + i4) = make_float4(0.f, 0.f, 0.f, 0.f);
    } else {
        for (long long j = i4; j < n; j++) p[j] = 0.f;
    }
}

// x (fp32) -> g_h16 (fp16), vectorized
__global__ void to_half_kernel(const float* __restrict__ x) {
    long long i = (long long)blockIdx.x * blockDim.x + threadIdx.x;
    long long q = i * 4;
    if (q >= (long long)NN * 128) return;
    float4 v = *(const float4*)(x + q);
    __half2 a = __floats2half2_rn(v.x, v.y);
    __half2 b = __floats2half2_rn(v.z, v.w);
    uint2 st; st.x = *(uint32_t*)&a; st.y = *(uint32_t*)&b;
    *(uint2*)(g_h16 + q) = st;
}

// ---------------- CSR build ----------------
__global__ void zero_cnt_kernel() {
    int i = blockIdx.x * blockDim.x + threadIdx.x;
    if (i < NN) g_cnt[i] = 0;
}

__global__ void hist_kernel(const void* eidx) {
    int is64 = g_flags[0];
    long long i = (long long)blockIdx.x * blockDim.x + threadIdx.x;
    if (i < EE) {
        int dst = load_idx(eidx, (long long)EE + i, is64);
        atomicAdd(&g_cnt[dst], 1);
    }
}

__global__ void scan1_kernel() {
    __shared__ int sh[1024];
    int i = blockIdx.x * 1024 + threadIdx.x;
    int v = (i < NN) ? g_cnt[i] : 0;
    sh[threadIdx.x] = v;
    __syncthreads();
    for (int o = 1; o < 1024; o <<= 1) {
        int t = (threadIdx.x >= o) ? sh[threadIdx.x - o] : 0;
        __syncthreads();
        sh[threadIdx.x] += t;
        __syncthreads();
    }
    if (i < NN) g_off[i] = sh[threadIdx.x] - v;
    if (threadIdx.x == 1023) g_bsums[blockIdx.x] = sh[1023];
}

__global__ void scan2_kernel() {
    if (threadIdx.x == 0) {
        int run = 0;
        for (int b = 0; b < NBLK; b++) { g_bscan[b] = run; run += g_bsums[b]; }
        g_off[NN] = run;
    }
}

__global__ void scan3_kernel() {
    int i = blockIdx.x * blockDim.x + threadIdx.x;
    if (i < NN) {
        int o = g_off[i] + g_bscan[i >> 10];
        g_off[i] = o;
        g_cursor[i] = o;
        float d = (float)g_cnt[i];
        g_norm[i] = (d > 0.f) ? rsqrtf(fmaxf(d, 1.0f)) : 0.f;
    }
}

__global__ void fill_kernel(const void* eidx) {
    int is64 = g_flags[0];
    long long e = (long long)blockIdx.x * blockDim.x + threadIdx.x;
    if (e < EE) {
        int src = load_idx(eidx, e, is64);
        int dst = load_idx(eidx, (long long)EE + e, is64);
        int pos = atomicAdd(&g_cursor[dst], 1);
        g_csr_src[pos] = src;
        g_csr_norm[pos] = g_norm[src];
    }
}

// ---------------- gather propagation (one warp per dst row, fp16 rows) ----------------
// sq=0: out[d] = sum h[src]*norm[src]      sq=1: sum h[src]*norm[src]^2
// zstats: block 0 additionally zeroes g_stats (BN-stats reset for this layer)
// Inner loop unrolled x4: 4 independent LDG.64 in flight per dependent step.
__global__ void gather_kernel(const __half* __restrict__ h, __half* __restrict__ out,
                              int sq, int zstats) {
    if (zstats && blockIdx.x == 0 && threadIdx.x < 256) g_stats[threadIdx.x] = 0.f;
    int w = blockIdx.x * (blockDim.x >> 5) + (threadIdx.x >> 5);
    if (w >= NN) return;
    int lane = threadIdx.x & 31;
    int s = g_off[w], e = g_off[w + 1];
    float4 acc = make_float4(0.f, 0.f, 0.f, 0.f);
    for (int j = s; j < e; j += 32) {
        int n = min(32, e - j);
        int  idx = 0;
        float nm = 0.f;
        if (lane < n) {
            idx = g_csr_src[j + lane];
            nm  = g_csr_norm[j + lane];
            if (sq) nm *= nm;
        }
        int k = 0;
        for (; k + 3 < n; k += 4) {
            int   s0 = __shfl_sync(0xffffffffu, idx, k);
            int   s1 = __shfl_sync(0xffffffffu, idx, k + 1);
            int   s2 = __shfl_sync(0xffffffffu, idx, k + 2);
            int   s3 = __shfl_sync(0xffffffffu, idx, k + 3);
            float n0 = __shfl_sync(0xffffffffu, nm, k);
            float n1 = __shfl_sync(0xffffffffu, nm, k + 1);
            float n2 = __shfl_sync(0xffffffffu, nm, k + 2);
            float n3 = __shfl_sync(0xffffffffu, nm, k + 3);
            uint2 u0 = __ldg((const uint2*)(h + (size_t)s0 * 128) + lane);
            uint2 u1 = __ldg((const uint2*)(h + (size_t)s1 * 128) + lane);
            uint2 u2 = __ldg((const uint2*)(h + (size_t)s2 * 128) + lane);
            uint2 u3 = __ldg((const uint2*)(h + (size_t)s3 * 128) + lane);
            float2 a0 = __half22float2(*(__half2*)&u0.x), b0 = __half22float2(*(__half2*)&u0.y);
            float2 a1 = __half22float2(*(__half2*)&u1.x), b1 = __half22float2(*(__half2*)&u1.y);
            float2 a2 = __half22float2(*(__half2*)&u2.x), b2 = __half22float2(*(__half2*)&u2.y);
            float2 a3 = __half22float2(*(__half2*)&u3.x), b3 = __half22float2(*(__half2*)&u3.y);
            acc.x += a0.x * n0 + a1.x * n1 + a2.x * n2 + a3.x * n3;
            acc.y += a0.y * n0 + a1.y * n1 + a2.y * n2 + a3.y * n3;
            acc.z += b0.x * n0 + b1.x * n1 + b2.x * n2 + b3.x * n3;
            acc.w += b0.y * n0 + b1.y * n1 + b2.y * n2 + b3.y * n3;
        }
        for (; k < n; k++) {
            int   s0 = __shfl_sync(0xffffffffu, idx, k);
            float n0 = __shfl_sync(0xffffffffu, nm, k);
            uint2 u0 = __ldg((const uint2*)(h + (size_t)s0 * 128) + lane);
            float2 a0 = __half22float2(*(__half2*)&u0.x);
            float2 b0 = __half22float2(*(__half2*)&u0.y);
            acc.x += a0.x * n0; acc.y += a0.y * n0;
            acc.z += b0.x * n0; acc.w += b0.y * n0;
        }
    }
    __half2 o0 = __floats2half2_rn(acc.x, acc.y);
    __half2 o1 = __floats2half2_rn(acc.z, acc.w);
    uint2 st; st.x = *(uint32_t*)&o0; st.y = *(uint32_t*)&o1;
    *((uint2*)(out + (size_t)w * 128) + lane) = st;
}

// ------------- bf16 split prep for ALL weight matrices (one launch) -------------
__global__ void prep_w_all_kernel(const float* __restrict__ convW,
                                  const float* __restrict__ convWlast) {
    int idx = blockIdx.x * blockDim.x + threadIdx.x;
    if (idx >= WSZ) return;
    float v;
    if (idx < 5 * 49152) {
        int l = idx / 49152, r = idx % 49152;
        int n = r / 384, k = r % 384;
        v = convW[(size_t)l * 49152 + (size_t)k * 128 + n];
    } else {
        int r = idx - 5 * 49152;
        int n = r / 384, k = r % 384;
        v = convWlast[(size_t)k * 64 + n];
    }
    __nv_bfloat16 hi = __float2bfloat16(v);
    g_bh[idx] = hi;
    g_bl[idx] = __float2bfloat16(v - __bfloat162float(hi));
}

// ------------- WMMA bf16 GEMM, fused hi/lo split + fused BN column stats -------------
__device__ __forceinline__ void split4_store(__nv_bfloat16* s_ah, __nv_bfloat16* s_al, int so,
                                             float a0, float a1, float a2, float a3) {
    __nv_bfloat16 h0 = __float2bfloat16(a0), h1 = __float2bfloat16(a1);
    __nv_bfloat16 h2 = __float2bfloat16(a2), h3 = __float2bfloat16(a3);
    __nv_bfloat162 hp0; hp0.x = h0; hp0.y = h1;
    __nv_bfloat162 hp1; hp1.x = h2; hp1.y = h3;
    __nv_bfloat162 lp0, lp1;
    lp0.x = __float2bfloat16(a0 - __bfloat162float(h0));
    lp0.y = __float2bfloat16(a1 - __bfloat162float(h1));
    lp1.x = __float2bfloat16(a2 - __bfloat162float(h2));
    lp1.y = __float2bfloat16(a3 - __bfloat162float(h3));
    *(__nv_bfloat162*)(s_ah + so)     = hp0;
    *(__nv_bfloat162*)(s_ah + so + 2) = hp1;
    *(__nv_bfloat162*)(s_al + so)     = lp0;
    *(__nv_bfloat162*)(s_al + so + 2) = lp1;
}

template<int DOUT>
__global__ void __launch_bounds__(DOUT == 128 ? 256 : 128, 1)
wmma_gemm_kernel(const float* __restrict__ A0, const __half* __restrict__ A1,
                 const __half* __restrict__ A2,
                 const __nv_bfloat16* __restrict__ Bh, const __nv_bfloat16* __restrict__ Bl,
                 float* __restrict__ Y) {
    constexpr int NT  = (DOUT == 128) ? 256 : 128;
    constexpr int LDS = 136;  // 128 + 8 pad
    extern __shared__ __nv_bfloat16 sm[];
    __nv_bfloat16* s_ah = sm;                       // 64  x LDS
    __nv_bfloat16* s_al = s_ah + 64 * LDS;
    __nv_bfloat16* s_bh = s_al + 64 * LDS;          // DOUT x LDS
    __nv_bfloat16* s_bl = s_bh + DOUT * LDS;

    int tid = threadIdx.x;
    int wid = tid >> 5;
    int wm = wid & 3;
    int wn = wid >> 2;
    int row0 = blockIdx.x * 64;

    wmma::fragment<wmma::accumulator, 16, 16, 16, float> acc[4];
#pragma unroll
    for (int j = 0; j < 4; j++) wmma::fill_fragment(acc[j], 0.f);

#pragma unroll
    for (int kc = 0; kc < 3; kc++) {
        // Stage A chunk: 64 rows x 128 k -> hi/lo bf16 (norm folded for kc>0)
        if (kc == 0) {
            for (int q = tid; q < 64 * 32; q += NT) {
                int m = q >> 5;
                int k4 = (q & 31) * 4;
                int r = row0 + m;
                float4 v = *(const float4*)(A0 + (size_t)r * 128 + k4);
                split4_store(s_ah, s_al, m * LDS + k4, v.x, v.y, v.z, v.w);
            }
        } else {
            const __half* A = (kc == 1) ? A1 : A2;
            for (int q = tid; q < 64 * 32; q += NT) {
                int m = q >> 5;
                int k4 = (q & 31) * 4;
                int r = row0 + m;
                float f = g_norm[r];
                uint2 u = *(const uint2*)(A + (size_t)r * 128 + k4);
                float2 a = __half22float2(*(__half2*)&u.x);
                float2 b = __half22float2(*(__half2*)&u.y);
                split4_store(s_ah, s_al, m * LDS + k4, a.x * f, a.y * f, b.x * f, b.y * f);
            }
        }
        for (int q = tid; q < DOUT * 16; q += NT) {
            int n = q >> 4;
            int k8 = (q & 15) * 8;
            size_t gi = (size_t)n * 384 + kc * 128 + k8;
            int so = n * LDS + k8;
            *(uint4*)(s_bh + so) = *(const uint4*)(Bh + gi);
            *(uint4*)(s_bl + so) = *(const uint4*)(Bl + gi);
        }
        __syncthreads();

#pragma unroll
        for (int ks = 0; ks < 8; ks++) {
            wmma::fragment<wmma::matrix_a, 16, 16, 16, __nv_bfloat16, wmma::row_major> fah, fal;
            wmma::load_matrix_sync(fah, s_ah + wm * 16 * LDS + ks * 16, LDS);
            wmma::load_matrix_sync(fal, s_al + wm * 16 * LDS + ks * 16, LDS);
#pragma unroll
            for (int j = 0; j < 4; j++) {
                wmma::fragment<wmma::matrix_b, 16, 16, 16, __nv_bfloat16, wmma::col_major> fbh, fbl;
                int n0 = wn * 64 + j * 16;
                wmma::load_matrix_sync(fbh, s_bh + n0 * LDS + ks * 16, LDS);
                wmma::load_matrix_sync(fbl, s_bl + n0 * LDS + ks * 16, LDS);
                wmma::mma_sync(acc[j], fah, fbh, acc[j]);
                wmma::mma_sync(acc[j], fah, fbl, acc[j]);
                wmma::mma_sync(acc[j], fal, fbh, acc[j]);
            }
        }
        __syncthreads();
    }

    // Epilogue: stage result tile in smem (reuse), write Y, fused column stats
    float* s_y = (float*)sm;  // 64 x DOUT floats
#pragma unroll
    for (int j = 0; j < 4; j++) {
        wmma::store_matrix_sync(s_y + (wm * 16) * DOUT + wn * 64 + j * 16,
                                acc[j], DOUT, wmma::mem_row_major);
    }
    __syncthreads();
    for (int q = tid; q < 64 * (DOUT / 4); q += NT) {
        int r = q / (DOUT / 4);
        int c4 = (q % (DOUT / 4)) * 4;
        *(float4*)(Y + (size_t)(row0 + r) * DOUT + c4) = *(float4*)(s_y + r * DOUT + c4);
    }
    {
        int col = tid % DOUT;
        int hh = tid / DOUT;   // 0 or 1; rows [hh*32, hh*32+32)
        float s = 0.f, ss = 0.f;
        for (int r = hh * 32; r < hh * 32 + 32; r++) {
            float v = s_y[r * DOUT + col];
            s += v; ss += v * v;
        }
        atomicAdd(&g_stats[col], s);
        atomicAdd(&g_stats[DOUT + col], ss);
    }
}

// ------------- BN apply (+ReLU +skip, writes fp32 out and fp16 copy) -------------
__global__ void bn_apply_kernel(const float* __restrict__ y, const float* __restrict__ stats,
                                const float* __restrict__ gamma, const float* __restrict__ beta,
                                const float* __restrict__ skip, float* __restrict__ out,
                                __half* __restrict__ out16, int d) {
    __shared__ float sc[128], sh[128];
    if (threadIdx.x < d) {
        float m = stats[threadIdx.x] / (float)NN;
        float v = stats[d + threadIdx.x] / (float)NN - m * m;
        float inv = rsqrtf(v + 1e-5f);
        float gi = gamma[threadIdx.x] * inv;
        sc[threadIdx.x] = gi;
        sh[threadIdx.x] = beta[threadIdx.x] - m * gi;
    }
    __syncthreads();
    long long total = (long long)NN * d / 2;
    long long stride = (long long)gridDim.x * blockDim.x;
    for (long long t = (long long)blockIdx.x * blockDim.x + threadIdx.x; t < total; t += stride) {
        long long i = t * 2;
        int f = (int)(i & (d - 1));
        float2 yv = *(const float2*)(y + i);
        float v0 = yv.x * sc[f] + sh[f];
        float v1 = yv.y * sc[f + 1] + sh[f + 1];
        v0 = fmaxf(v0, 0.f); v1 = fmaxf(v1, 0.f);
        if (skip) {
            float2 sv = *(const float2*)(skip + i);
            v0 += sv.x; v1 += sv.y;
        }
        *(float2*)(out + i) = make_float2(v0, v1);
        __half2 hv = __floats2half2_rn(v0, v1);
        *(__half2*)(out16 + i) = hv;
    }
}

// ------------- pooling / head -------------
__global__ void seg_starts_kernel(const void* seg) {
    int is64 = g_flags[1];
    long long i = (long long)blockIdx.x * blockDim.x + threadIdx.x;
    if (i >= NN) return;
    int s = load_idx(seg, i, is64);
    if (i == 0) {
        for (int g = 0; g <= s; g++) g_starts[g] = 0;
    } else {
        int sp = load_idx(seg, i - 1, is64);
        for (int g = sp + 1; g <= s; g++) g_starts[g] = (int)i;
    }
    if (i == NN - 1) {
        for (int g = s + 1; g <= GG; g++) g_starts[g] = NN;
    }
}

__global__ void pool_kernel(const float* __restrict__ h) {
    int g = blockIdx.x, f = threadIdx.x;
    int s = g_starts[g], e = g_starts[g + 1];
    float mx = -3.4e38f, mn = 3.4e38f, sum = 0.f, ssq = 0.f;
    for (int n = s; n < e; n++) {
        float v = h[(size_t)n * 64 + f];
        mx = fmaxf(mx, v); mn = fminf(mn, v);
        sum += v; ssq += v * v;
    }
    float c = (float)(e - s);
    float mean = sum / fmaxf(c, 1.f);
    float var = (ssq - c * mean * mean) / fmaxf(c - 1.f, 1.f);
    float sd = sqrtf(fmaxf(var, 0.f));
    float* P = g_pool + (size_t)g * 256;
    P[f] = mx; P[64 + f] = mn; P[128 + f] = mean; P[192 + f] = sd;
}

__global__ void agg_stats_kernel() {
    __shared__ float loc[8];
    if (threadIdx.x < 8) loc[threadIdx.x] = 0.f;
    __syncthreads();
    float s0 = 0, s1 = 0, s2 = 0, s3 = 0, q0 = 0, q1 = 0, q2 = 0, q3 = 0;
    long long total = (long long)GG * 256;
    long long stride = (long long)gridDim.x * blockDim.x;
    for (long long i = (long long)blockIdx.x * blockDim.x + threadIdx.x; i < total; i += stride) {
        int c = (int)((i >> 6) & 3);
        float v = g_pool[i];
        if (c == 0)      { s0 += v; q0 += v * v; }
        else if (c == 1) { s1 += v; q1 += v * v; }
        else if (c == 2) { s2 += v; q2 += v * v; }
        else             { s3 += v; q3 += v * v; }
    }
    atomicAdd(&loc[0], s0); atomicAdd(&loc[4], q0);
    atomicAdd(&loc[1], s1); atomicAdd(&loc[5], q1);
    atomicAdd(&loc[2], s2); atomicAdd(&loc[6], q2);
    atomicAdd(&loc[3], s3); atomicAdd(&loc[7], q3);
    __syncthreads();
    if (threadIdx.x < 8) atomicAdd(&g_aggstats[threadIdx.x], loc[threadIdx.x]);
}

__global__ void final_kernel(const float* __restrict__ aggW, const float* __restrict__ aggB,
                             const float* __restrict__ agg_gamma, const float* __restrict__ agg_beta,
                             const float* __restrict__ outW, const float* __restrict__ outB,
                             float* __restrict__ out) {
    __shared__ float flat[256];
    __shared__ float red[2];
    int g = blockIdx.x, t = threadIdx.x;
    float cnt = (float)GG * 64.f;
#pragma unroll
    for (int c = 0; c < 4; c++) {
        float m = g_aggstats[c] / cnt;
        float v = g_aggstats[4 + c] / cnt - m * m;
        float inv = rsqrtf(v + 1e-5f);
        float x = g_pool[(size_t)g * 256 + c * 64 + t];
        flat[c * 64 + t] = (x - m) * inv * agg_gamma[c] + agg_beta[c];
    }
    __syncthreads();
    float hg = aggB[t];
#pragma unroll 8
    for (int j = 0; j < 256; j++) hg += flat[j] * aggW[t * 256 + j];
    float val = hg * outW[t];
#pragma unroll
    for (int o = 16; o > 0; o >>= 1) val += __shfl_down_sync(0xffffffff, val, o);
    if ((t & 31) == 0) red[t >> 5] = val;
    __syncthreads();
    if (t == 0) out[g] = red[0] + red[1] + outB[0];
}

// ---------------- host ----------------
static inline void zero_launch(float* p, long long n) {
    long long n4 = (n + 3) / 4;
    int blocks = (int)((n4 + 255) / 256);
    zero_kernel<<<blocks, 256>>>(p, n);
}

extern "C" void kernel_launch(void* const* d_in, const int* in_sizes, int n_in,
                              void* d_out, int out_size) {
    const float* x            = (const float*)d_in[0];
    const void*  eidx         = d_in[1];
    const void*  seg          = d_in[2];
    const float* conv_W       = (const float*)d_in[3];
    const float* conv_W_last  = (const float*)d_in[4];
    const float* bn_gamma     = (const float*)d_in[5];
    const float* bn_beta      = (const float*)d_in[6];
    const float* bn_gamma_l   = (const float*)d_in[7];
    const float* bn_beta_l    = (const float*)d_in[8];
    const float* agg_gamma    = (const float*)d_in[9];
    const float* agg_beta     = (const float*)d_in[10];
    const float* aggW         = (const float*)d_in[11];
    const float* aggB         = (const float*)d_in[12];
    const float* outW         = (const float*)d_in[13];
    const float* outB         = (const float*)d_in[14];
    float* out = (float*)d_out;

    float *y, *o0, *o1, *o2, *stats, *aggstats;
    __half *h16, *p1h, *p2h;
    __nv_bfloat16 *bh, *bl;
    cudaGetSymbolAddress((void**)&y, g_y);
    cudaGetSymbolAddress((void**)&o0, g_o0);
    cudaGetSymbolAddress((void**)&o1, g_o1);
    cudaGetSymbolAddress((void**)&o2, g_o2);
    cudaGetSymbolAddress((void**)&stats, g_stats);
    cudaGetSymbolAddress((void**)&aggstats, g_aggstats);
    cudaGetSymbolAddress((void**)&h16, g_h16);
    cudaGetSymbolAddress((void**)&p1h, g_p1h);
    cudaGetSymbolAddress((void**)&p2h, g_p2h);
    cudaGetSymbolAddress((void**)&bh, g_bh);
    cudaGetSymbolAddress((void**)&bl, g_bl);

    const int SMEM128 = (64 * 2 + 128 * 2) * 136 * 2;  // 104448 (>= 64*128*4 float tile)
    const int SMEM64  = (64 * 2 +  64 * 2) * 136 * 2;  //  69632 (>= 64*64*4)
    cudaFuncSetAttribute(wmma_gemm_kernel<128>,
                         cudaFuncAttributeMaxDynamicSharedMemorySize, SMEM128);
    cudaFuncSetAttribute(wmma_gemm_kernel<64>,
                         cudaFuncAttributeMaxDynamicSharedMemorySize, SMEM64);

    detect_kernel<<<1, 32>>>((const unsigned*)eidx, (const unsigned*)seg);

    // ---- CSR build (by dst) + all-layer weight prep (off the layer chain) ----
    zero_cnt_kernel<<<(NN + 255) / 256, 256>>>();
    hist_kernel<<<(EE + 255) / 256, 256>>>(eidx);
    scan1_kernel<<<NBLK, 1024>>>();
    scan2_kernel<<<1, 32>>>();
    scan3_kernel<<<(NN + 255) / 256, 256>>>();
    fill_kernel<<<(EE + 255) / 256, 256>>>(eidx);
    prep_w_all_kernel<<<(WSZ + 255) / 256, 256>>>(conv_W, conv_W_last);

    // fp16 copy of x
    to_half_kernel<<<(int)(((long long)NN * 128 / 4 + 255) / 256), 256>>>(x);

    float* outs[6] = {o0, o1, o2, o0, o1, o2};
    const float* hin = x;
    const int gather_blocks = (NN + 7) / 8;            // 8 warps/block
    const int gemm_blocks = NN / 64;                   // 3125, exact

    for (int l = 0; l < 6; l++) {
        int dout = (l < 5) ? 128 : 64;
        const __nv_bfloat16* Bh = bh + (size_t)l * 49152;
        const __nv_bfloat16* Bl = bl + (size_t)l * 49152;
        const float* ga = (l < 5) ? bn_gamma + l * 128 : bn_gamma_l;
        const float* be = (l < 5) ? bn_beta  + l * 128 : bn_beta_l;
        const float* skip = (l >= 2 && l <= 4) ? outs[l - 2] : nullptr;

        gather_kernel<<<gather_blocks, 256>>>(h16, p1h, 0, 1);  // block 0 zeroes g_stats
        gather_kernel<<<gather_blocks, 256>>>(p1h, p2h, 1, 0);

        if (dout == 128)
            wmma_gemm_kernel<128><<<gemm_blocks, 256, SMEM128>>>(hin, p1h, p2h, Bh, Bl, y);
        else
            wmma_gemm_kernel<64><<<gemm_blocks, 128, SMEM64>>>(hin, p1h, p2h, Bh, Bl, y);

        bn_apply_kernel<<<4096, 256>>>(y, stats, ga, be, skip, outs[l], h16, dout);
        hin = outs[l];
    }

    seg_starts_kernel<<<(NN + 255) / 256, 256>>>(seg);
    pool_kernel<<<GG, 64>>>(hin);
    zero_launch(aggstats, 8);
    agg_stats_kernel<<<256, 256>>>();
    final_kernel<<<GG, 64>>>(aggW, aggB, agg_gamma, agg_beta, outW, outB, out);
}

// round 16
// speedup vs baseline: 1.0891x; 1.0891x over previous
#include <cuda_runtime.h>
#include <cuda_bf16.h>
#include <cuda_fp16.h>
#include <mma.h>
#include <cstdint>
#include <cstddef>

using namespace nvcuda;

#define NN 200000
#define EE 3200000
#define GG 2000
#define NBLK 196   // ceil(NN/1024)
#define WSZ (5 * 49152 + 24576)  // total W^T elements across 6 layers

// ---------------- device scratch (static, allocation-free) ----------------
__device__ int   g_cnt[NN];
__device__ int   g_off[NN + 1];
__device__ int   g_cursor[NN];
__device__ int   g_bsums[NBLK];
__device__ int   g_bscan[NBLK];
__device__ int   g_csr_src[EE];
__device__ float g_csr_norm[EE];
__device__ float g_norm[NN];
__device__ __half g_h16[(size_t)NN * 128];  // fp16 copy of current h (gather input)
__device__ __half g_p1h[(size_t)NN * 128];  // fp16 prop1
__device__ __half g_p2h[(size_t)NN * 128];  // fp16 prop2
__device__ float g_y [(size_t)NN * 128];    // GEMM output
__device__ float g_o0[(size_t)NN * 128];    // rotating layer outputs
__device__ float g_o1[(size_t)NN * 128];
__device__ float g_o2[(size_t)NN * 128];
__device__ __nv_bfloat16 g_bh[WSZ];         // W^T bf16 hi, all layers [l][n][k]
__device__ __nv_bfloat16 g_bl[WSZ];         // W^T bf16 lo
__device__ float g_stats[256];
__device__ int   g_starts[GG + 1];
__device__ float g_pool[(size_t)GG * 4 * 64];
__device__ float g_aggstats[8];
__device__ int   g_flags[2];

// ---------------- misc helpers ----------------
__device__ __forceinline__ int load_idx(const void* p, long long i, int is64) {
    if (is64) return (int)((const long long*)p)[i];
    return ((const int*)p)[i];
}

__global__ void detect_kernel(const unsigned* e, const unsigned* s) {
    if (threadIdx.x == 0 && blockIdx.x == 0) {
        int z = 1;
        for (int i = 1; i < 128; i += 2) if (e[i] != 0) { z = 0; break; }
        g_flags[0] = z;
        z = 1;
        for (int i = NN - 127; i < NN; i += 2) if (s[i] != 0) { z = 0; break; }
        g_flags[1] = z;
    }
}

__global__ void zero_kernel(float* p, long long n) {
    long long i = (long long)blockIdx.x * blockDim.x + threadIdx.x;
    long long i4 = i * 4;
    if (i4 + 3 < n) {
        *(float4*)(p + i4) = make_float4(0.f, 0.f, 0.f, 0.f);
    } else {
        for (long long j = i4; j < n; j++) p[j] = 0.f;
    }
}

// x (fp32) -> g_h16 (fp16), vectorized
__global__ void to_half_kernel(const float* __restrict__ x) {
    long long i = (long long)blockIdx.x * blockDim.x + threadIdx.x;
    long long q = i * 4;
    if (q >= (long long)NN * 128) return;
    float4 v = *(const float4*)(x + q);
    __half2 a = __floats2half2_rn(v.x, v.y);
    __half2 b = __floats2half2_rn(v.z, v.w);
    uint2 st; st.x = *(uint32_t*)&a; st.y = *(uint32_t*)&b;
    *(uint2*)(g_h16 + q) = st;
}

// ---------------- CSR build ----------------
__global__ void zero_cnt_kernel() {
    int i = blockIdx.x * blockDim.x + threadIdx.x;
    if (i < NN) g_cnt[i] = 0;
}

__global__ void hist_kernel(const void* eidx) {
    int is64 = g_flags[0];
    long long i = (long long)blockIdx.x * blockDim.x + threadIdx.x;
    if (i < EE) {
        int dst = load_idx(eidx, (long long)EE + i, is64);
        atomicAdd(&g_cnt[dst], 1);
    }
}

__global__ void scan1_kernel() {
    __shared__ int sh[1024];
    int i = blockIdx.x * 1024 + threadIdx.x;
    int v = (i < NN) ? g_cnt[i] : 0;
    sh[threadIdx.x] = v;
    __syncthreads();
    for (int o = 1; o < 1024; o <<= 1) {
        int t = (threadIdx.x >= o) ? sh[threadIdx.x - o] : 0;
        __syncthreads();
        sh[threadIdx.x] += t;
        __syncthreads();
    }
    if (i < NN) g_off[i] = sh[threadIdx.x] - v;
    if (threadIdx.x == 1023) g_bsums[blockIdx.x] = sh[1023];
}

__global__ void scan2_kernel() {
    if (threadIdx.x == 0) {
        int run = 0;
        for (int b = 0; b < NBLK; b++) { g_bscan[b] = run; run += g_bsums[b]; }
        g_off[NN] = run;
    }
}

__global__ void scan3_kernel() {
    int i = blockIdx.x * blockDim.x + threadIdx.x;
    if (i < NN) {
        int o = g_off[i] + g_bscan[i >> 10];
        g_off[i] = o;
        g_cursor[i] = o;
        float d = (float)g_cnt[i];
        g_norm[i] = (d > 0.f) ? rsqrtf(fmaxf(d, 1.0f)) : 0.f;
    }
}

__global__ void fill_kernel(const void* eidx) {
    int is64 = g_flags[0];
    long long e = (long long)blockIdx.x * blockDim.x + threadIdx.x;
    if (e < EE) {
        int src = load_idx(eidx, e, is64);
        int dst = load_idx(eidx, (long long)EE + e, is64);
        int pos = atomicAdd(&g_cursor[dst], 1);
        g_csr_src[pos] = src;
        g_csr_norm[pos] = g_norm[src];
    }
}

// ---------------- gather propagation (one warp per dst row, fp16 rows) ----------------
// sq=0: out[d] = sum h[src]*norm[src]      sq=1: sum h[src]*norm[src]^2
// zstats: block 0 additionally zeroes g_stats (BN-stats reset for this layer)
// Unroll-2 idiom (best measured across 5 variants).
__global__ void gather_kernel(const __half* __restrict__ h, __half* __restrict__ out,
                              int sq, int zstats) {
    if (zstats && blockIdx.x == 0 && threadIdx.x < 256) g_stats[threadIdx.x] = 0.f;
    int w = blockIdx.x * (blockDim.x >> 5) + (threadIdx.x >> 5);
    if (w >= NN) return;
    int lane = threadIdx.x & 31;
    int s = g_off[w], e = g_off[w + 1];
    float4 acc = make_float4(0.f, 0.f, 0.f, 0.f);
    for (int j = s; j < e; j += 32) {
        int n = min(32, e - j);
        int  idx = 0;
        float nm = 0.f;
        if (lane < n) {
            idx = g_csr_src[j + lane];
            nm  = g_csr_norm[j + lane];
            if (sq) nm *= nm;
        }
        int k = 0;
        for (; k + 1 < n; k += 2) {
            int   s0 = __shfl_sync(0xffffffffu, idx, k);
            int   s1 = __shfl_sync(0xffffffffu, idx, k + 1);
            float n0 = __shfl_sync(0xffffffffu, nm, k);
            float n1 = __shfl_sync(0xffffffffu, nm, k + 1);
            uint2 u0 = __ldg((const uint2*)(h + (size_t)s0 * 128) + lane);
            uint2 u1 = __ldg((const uint2*)(h + (size_t)s1 * 128) + lane);
            float2 a0 = __half22float2(*(__half2*)&u0.x);
            float2 b0 = __half22float2(*(__half2*)&u0.y);
            float2 a1 = __half22float2(*(__half2*)&u1.x);
            float2 b1 = __half22float2(*(__half2*)&u1.y);
            acc.x += a0.x * n0 + a1.x * n1;
            acc.y += a0.y * n0 + a1.y * n1;
            acc.z += b0.x * n0 + b1.x * n1;
            acc.w += b0.y * n0 + b1.y * n1;
        }
        if (k < n) {
            int   s0 = __shfl_sync(0xffffffffu, idx, k);
            float n0 = __shfl_sync(0xffffffffu, nm, k);
            uint2 u0 = __ldg((const uint2*)(h + (size_t)s0 * 128) + lane);
            float2 a0 = __half22float2(*(__half2*)&u0.x);
            float2 b0 = __half22float2(*(__half2*)&u0.y);
            acc.x += a0.x * n0; acc.y += a0.y * n0;
            acc.z += b0.x * n0; acc.w += b0.y * n0;
        }
    }
    __half2 o0 = __floats2half2_rn(acc.x, acc.y);
    __half2 o1 = __floats2half2_rn(acc.z, acc.w);
    uint2 st; st.x = *(uint32_t*)&o0; st.y = *(uint32_t*)&o1;
    *((uint2*)(out + (size_t)w * 128) + lane) = st;
}

// ------------- bf16 split prep for ALL weight matrices (one launch) -------------
__global__ void prep_w_all_kernel(const float* __restrict__ convW,
                                  const float* __restrict__ convWlast) {
    int idx = blockIdx.x * blockDim.x + threadIdx.x;
    if (idx >= WSZ) return;
    float v;
    if (idx < 5 * 49152) {
        int l = idx / 49152, r = idx % 49152;
        int n = r / 384, k = r % 384;
        v = convW[(size_t)l * 49152 + (size_t)k * 128 + n];
    } else {
        int r = idx - 5 * 49152;
        int n = r / 384, k = r % 384;
        v = convWlast[(size_t)k * 64 + n];
    }
    __nv_bfloat16 hi = __float2bfloat16(v);
    g_bh[idx] = hi;
    g_bl[idx] = __float2bfloat16(v - __bfloat162float(hi));
}

// ------------- WMMA bf16 GEMM (M-tile 128), fused hi/lo split + fused BN stats -------------
__device__ __forceinline__ void split4_store(__nv_bfloat16* s_ah, __nv_bfloat16* s_al, int so,
                                             float a0, float a1, float a2, float a3) {
    __nv_bfloat16 h0 = __float2bfloat16(a0), h1 = __float2bfloat16(a1);
    __nv_bfloat16 h2 = __float2bfloat16(a2), h3 = __float2bfloat16(a3);
    __nv_bfloat162 hp0; hp0.x = h0; hp0.y = h1;
    __nv_bfloat162 hp1; hp1.x = h2; hp1.y = h3;
    __nv_bfloat162 lp0, lp1;
    lp0.x = __float2bfloat16(a0 - __bfloat162float(h0));
    lp0.y = __float2bfloat16(a1 - __bfloat162float(h1));
    lp1.x = __float2bfloat16(a2 - __bfloat162float(h2));
    lp1.y = __float2bfloat16(a3 - __bfloat162float(h3));
    *(__nv_bfloat162*)(s_ah + so)     = hp0;
    *(__nv_bfloat162*)(s_ah + so + 2) = hp1;
    *(__nv_bfloat162*)(s_al + so)     = lp0;
    *(__nv_bfloat162*)(s_al + so + 2) = lp1;
}

template<int DOUT>
__global__ void __launch_bounds__(DOUT == 128 ? 512 : 256, 1)
wmma_gemm_kernel(const float* __restrict__ A0, const __half* __restrict__ A1,
                 const __half* __restrict__ A2,
                 const __nv_bfloat16* __restrict__ Bh, const __nv_bfloat16* __restrict__ Bl,
                 float* __restrict__ Y) {
    constexpr int NT  = (DOUT == 128) ? 512 : 256;   // 16 / 8 warps
    constexpr int LDS = 136;  // 128 + 8 pad
    extern __shared__ __nv_bfloat16 sm[];
    __nv_bfloat16* s_ah = sm;                        // 128  x LDS
    __nv_bfloat16* s_al = s_ah + 128 * LDS;
    __nv_bfloat16* s_bh = s_al + 128 * LDS;          // DOUT x LDS
    __nv_bfloat16* s_bl = s_bh + DOUT * LDS;

    int tid = threadIdx.x;
    int wid = tid >> 5;
    int wm = wid & 7;        // 8 m-warps x 16 rows = 128 rows
    int wn = wid >> 3;       // 2 n-warps (DOUT=128) or 1 (DOUT=64)
    int row0 = blockIdx.x * 128;

    wmma::fragment<wmma::accumulator, 16, 16, 16, float> acc[4];
#pragma unroll
    for (int j = 0; j < 4; j++) wmma::fill_fragment(acc[j], 0.f);

#pragma unroll
    for (int kc = 0; kc < 3; kc++) {
        // Stage A chunk: 128 rows x 128 k -> hi/lo bf16 (norm folded for kc>0; zero-pad tail rows)
        if (kc == 0) {
            for (int q = tid; q < 128 * 32; q += NT) {
                int m = q >> 5;
                int k4 = (q & 31) * 4;
                int r = row0 + m;
                float4 v = make_float4(0.f, 0.f, 0.f, 0.f);
                if (r < NN) v = *(const float4*)(A0 + (size_t)r * 128 + k4);
                split4_store(s_ah, s_al, m * LDS + k4, v.x, v.y, v.z, v.w);
            }
        } else {
            const __half* A = (kc == 1) ? A1 : A2;
            for (int q = tid; q < 128 * 32; q += NT) {
                int m = q >> 5;
                int k4 = (q & 31) * 4;
                int r = row0 + m;
                float4 v = make_float4(0.f, 0.f, 0.f, 0.f);
                if (r < NN) {
                    float f = g_norm[r];
                    uint2 u = *(const uint2*)(A + (size_t)r * 128 + k4);
                    float2 a = __half22float2(*(__half2*)&u.x);
                    float2 b = __half22float2(*(__half2*)&u.y);
                    v = make_float4(a.x * f, a.y * f, b.x * f, b.y * f);
                }
                split4_store(s_ah, s_al, m * LDS + k4, v.x, v.y, v.z, v.w);
            }
        }
        for (int q = tid; q < DOUT * 16; q += NT) {
            int n = q >> 4;
            int k8 = (q & 15) * 8;
            size_t gi = (size_t)n * 384 + kc * 128 + k8;
            int so = n * LDS + k8;
            *(uint4*)(s_bh + so) = *(const uint4*)(Bh + gi);
            *(uint4*)(s_bl + so) = *(const uint4*)(Bl + gi);
        }
        __syncthreads();

#pragma unroll
        for (int ks = 0; ks < 8; ks++) {
            wmma::fragment<wmma::matrix_a, 16, 16, 16, __nv_bfloat16, wmma::row_major> fah, fal;
            wmma::load_matrix_sync(fah, s_ah + wm * 16 * LDS + ks * 16, LDS);
            wmma::load_matrix_sync(fal, s_al + wm * 16 * LDS + ks * 16, LDS);
#pragma unroll
            for (int j = 0; j < 4; j++) {
                wmma::fragment<wmma::matrix_b, 16, 16, 16, __nv_bfloat16, wmma::col_major> fbh, fbl;
                int n0 = wn * 64 + j * 16;
                wmma::load_matrix_sync(fbh, s_bh + n0 * LDS + ks * 16, LDS);
                wmma::load_matrix_sync(fbl, s_bl + n0 * LDS + ks * 16, LDS);
                wmma::mma_sync(acc[j], fah, fbh, acc[j]);
                wmma::mma_sync(acc[j], fah, fbl, acc[j]);
                wmma::mma_sync(acc[j], fal, fbh, acc[j]);
            }
        }
        __syncthreads();
    }

    // Epilogue: stage result tile in smem (reuse), write Y (guarded), fused column stats
    float* s_y = (float*)sm;  // 128 x DOUT floats
#pragma unroll
    for (int j = 0; j < 4; j++) {
        wmma::store_matrix_sync(s_y + (wm * 16) * DOUT + wn * 64 + j * 16,
                                acc[j], DOUT, wmma::mem_row_major);
    }
    __syncthreads();
    for (int q = tid; q < 128 * (DOUT / 4); q += NT) {
        int r = q / (DOUT / 4);
        int c4 = (q % (DOUT / 4)) * 4;
        if (row0 + r < NN)
            *(float4*)(Y + (size_t)(row0 + r) * DOUT + c4) = *(float4*)(s_y + r * DOUT + c4);
    }
    {
        // NT/DOUT = 4 row-groups of 32 rows each; padded rows are exact zeros -> stats safe
        int col = tid % DOUT;
        int hh = tid / DOUT;   // 0..3
        float s = 0.f, ss = 0.f;
        for (int r = hh * 32; r < hh * 32 + 32; r++) {
            float v = s_y[r * DOUT + col];
            s += v; ss += v * v;
        }
        atomicAdd(&g_stats[col], s);
        atomicAdd(&g_stats[DOUT + col], ss);
    }
}

// ------------- BN apply (+ReLU +skip, writes fp32 out and fp16 copy) -------------
__global__ void bn_apply_kernel(const float* __restrict__ y, const float* __restrict__ stats,
                                const float* __restrict__ gamma, const float* __restrict__ beta,
                                const float* __restrict__ skip, float* __restrict__ out,
                                __half* __restrict__ out16, int d) {
    __shared__ float sc[128], sh[128];
    if (threadIdx.x < d) {
        float m = stats[threadIdx.x] / (float)NN;
        float v = stats[d + threadIdx.x] / (float)NN - m * m;
        float inv = rsqrtf(v + 1e-5f);
        float gi = gamma[threadIdx.x] * inv;
        sc[threadIdx.x] = gi;
        sh[threadIdx.x] = beta[threadIdx.x] - m * gi;
    }
    __syncthreads();
    long long total = (long long)NN * d / 2;
    long long stride = (long long)gridDim.x * blockDim.x;
    for (long long t = (long long)blockIdx.x * blockDim.x + threadIdx.x; t < total; t += stride) {
        long long i = t * 2;
        int f = (int)(i & (d - 1));
        float2 yv = *(const float2*)(y + i);
        float v0 = yv.x * sc[f] + sh[f];
        float v1 = yv.y * sc[f + 1] + sh[f + 1];
        v0 = fmaxf(v0, 0.f); v1 = fmaxf(v1, 0.f);
        if (skip) {
            float2 sv = *(const float2*)(skip + i);
            v0 += sv.x; v1 += sv.y;
        }
        *(float2*)(out + i) = make_float2(v0, v1);
        __half2 hv = __floats2half2_rn(v0, v1);
        *(__half2*)(out16 + i) = hv;
    }
}

// ------------- pooling / head -------------
__global__ void seg_starts_kernel(const void* seg) {
    int is64 = g_flags[1];
    long long i = (long long)blockIdx.x * blockDim.x + threadIdx.x;
    if (i >= NN) return;
    int s = load_idx(seg, i, is64);
    if (i == 0) {
        for (int g = 0; g <= s; g++) g_starts[g] = 0;
    } else {
        int sp = load_idx(seg, i - 1, is64);
        for (int g = sp + 1; g <= s; g++) g_starts[g] = (int)i;
    }
    if (i == NN - 1) {
        for (int g = s + 1; g <= GG; g++) g_starts[g] = NN;
    }
}

__global__ void pool_kernel(const float* __restrict__ h) {
    int g = blockIdx.x, f = threadIdx.x;
    int s = g_starts[g], e = g_starts[g + 1];
    float mx = -3.4e38f, mn = 3.4e38f, sum = 0.f, ssq = 0.f;
    for (int n = s; n < e; n++) {
        float v = h[(size_t)n * 64 + f];
        mx = fmaxf(mx, v); mn = fminf(mn, v);
        sum += v; ssq += v * v;
    }
    float c = (float)(e - s);
    float mean = sum / fmaxf(c, 1.f);
    float var = (ssq - c * mean * mean) / fmaxf(c - 1.f, 1.f);
    float sd = sqrtf(fmaxf(var, 0.f));
    float* P = g_pool + (size_t)g * 256;
    P[f] = mx; P[64 + f] = mn; P[128 + f] = mean; P[192 + f] = sd;
}

__global__ void agg_stats_kernel() {
    __shared__ float loc[8];
    if (threadIdx.x < 8) loc[threadIdx.x] = 0.f;
    __syncthreads();
    float s0 = 0, s1 = 0, s2 = 0, s3 = 0, q0 = 0, q1 = 0, q2 = 0, q3 = 0;
    long long total = (long long)GG * 256;
    long long stride = (long long)gridDim.x * blockDim.x;
    for (long long i = (long long)blockIdx.x * blockDim.x + threadIdx.x; i < total; i += stride) {
        int c = (int)((i >> 6) & 3);
        float v = g_pool[i];
        if (c == 0)      { s0 += v; q0 += v * v; }
        else if (c == 1) { s1 += v; q1 += v * v; }
        else if (c == 2) { s2 += v; q2 += v * v; }
        else             { s3 += v; q3 += v * v; }
    }
    atomicAdd(&loc[0], s0); atomicAdd(&loc[4], q0);
    atomicAdd(&loc[1], s1); atomicAdd(&loc[5], q1);
    atomicAdd(&loc[2], s2); atomicAdd(&loc[6], q2);
    atomicAdd(&loc[3], s3); atomicAdd(&loc[7], q3);
    __syncthreads();
    if (threadIdx.x < 8) atomicAdd(&g_aggstats[threadIdx.x], loc[threadIdx.x]);
}

__global__ void final_kernel(const float* __restrict__ aggW, const float* __restrict__ aggB,
                             const float* __restrict__ agg_gamma, const float* __restrict__ agg_beta,
                             const float* __restrict__ outW, const float* __restrict__ outB,
                             float* __restrict__ out) {
    __shared__ float flat[256];
    __shared__ float red[2];
    int g = blockIdx.x, t = threadIdx.x;
    float cnt = (float)GG * 64.f;
#pragma unroll
    for (int c = 0; c < 4; c++) {
        float m = g_aggstats[c] / cnt;
        float v = g_aggstats[4 + c] / cnt - m * m;
        float inv = rsqrtf(v + 1e-5f);
        float x = g_pool[(size_t)g * 256 + c * 64 + t];
        flat[c * 64 + t] = (x - m) * inv * agg_gamma[c] + agg_beta[c];
    }
    __syncthreads();
    float hg = aggB[t];
#pragma unroll 8
    for (int j = 0; j < 256; j++) hg += flat[j] * aggW[t * 256 + j];
    float val = hg * outW[t];
#pragma unroll
    for (int o = 16; o > 0; o >>= 1) val += __shfl_down_sync(0xffffffff, val, o);
    if ((t & 31) == 0) red[t >> 5] = val;
    __syncthreads();
    if (t == 0) out[g] = red[0] + red[1] + outB[0];
}

// ---------------- host ----------------
static inline void zero_launch(float* p, long long n) {
    long long n4 = (n + 3) / 4;
    int blocks = (int)((n4 + 255) / 256);
    zero_kernel<<<blocks, 256>>>(p, n);
}

extern "C" void kernel_launch(void* const* d_in, const int* in_sizes, int n_in,
                              void* d_out, int out_size) {
    const float* x            = (const float*)d_in[0];
    const void*  eidx         = d_in[1];
    const void*  seg          = d_in[2];
    const float* conv_W       = (const float*)d_in[3];
    const float* conv_W_last  = (const float*)d_in[4];
    const float* bn_gamma     = (const float*)d_in[5];
    const float* bn_beta      = (const float*)d_in[6];
    const float* bn_gamma_l   = (const float*)d_in[7];
    const float* bn_beta_l    = (const float*)d_in[8];
    const float* agg_gamma    = (const float*)d_in[9];
    const float* agg_beta     = (const float*)d_in[10];
    const float* aggW         = (const float*)d_in[11];
    const float* aggB         = (const float*)d_in[12];
    const float* outW         = (const float*)d_in[13];
    const float* outB         = (const float*)d_in[14];
    float* out = (float*)d_out;

    float *y, *o0, *o1, *o2, *stats, *aggstats;
    __half *h16, *p1h, *p2h;
    __nv_bfloat16 *bh, *bl;
    cudaGetSymbolAddress((void**)&y, g_y);
    cudaGetSymbolAddress((void**)&o0, g_o0);
    cudaGetSymbolAddress((void**)&o1, g_o1);
    cudaGetSymbolAddress((void**)&o2, g_o2);
    cudaGetSymbolAddress((void**)&stats, g_stats);
    cudaGetSymbolAddress((void**)&aggstats, g_aggstats);
    cudaGetSymbolAddress((void**)&h16, g_h16);
    cudaGetSymbolAddress((void**)&p1h, g_p1h);
    cudaGetSymbolAddress((void**)&p2h, g_p2h);
    cudaGetSymbolAddress((void**)&bh, g_bh);
    cudaGetSymbolAddress((void**)&bl, g_bl);

    // smem: A(128 rows hi+lo) + B(DOUT rows hi+lo), LDS=136 bf16
    const int SMEM128 = (128 * 2 + 128 * 2) * 136 * 2;  // 139264
    const int SMEM64  = (128 * 2 +  64 * 2) * 136 * 2;  // 104448
    cudaFuncSetAttribute(wmma_gemm_kernel<128>,
                         cudaFuncAttributeMaxDynamicSharedMemorySize, SMEM128);
    cudaFuncSetAttribute(wmma_gemm_kernel<64>,
                         cudaFuncAttributeMaxDynamicSharedMemorySize, SMEM64);

    detect_kernel<<<1, 32>>>((const unsigned*)eidx, (const unsigned*)seg);

    // ---- CSR build (by dst) + all-layer weight prep (off the layer chain) ----
    zero_cnt_kernel<<<(NN + 255) / 256, 256>>>();
    hist_kernel<<<(EE + 255) / 256, 256>>>(eidx);
    scan1_kernel<<<NBLK, 1024>>>();
    scan2_kernel<<<1, 32>>>();
    scan3_kernel<<<(NN + 255) / 256, 256>>>();
    fill_kernel<<<(EE + 255) / 256, 256>>>(eidx);
    prep_w_all_kernel<<<(WSZ + 255) / 256, 256>>>(conv_W, conv_W_last);

    // fp16 copy of x
    to_half_kernel<<<(int)(((long long)NN * 128 / 4 + 255) / 256), 256>>>(x);

    float* outs[6] = {o0, o1, o2, o0, o1, o2};
    const float* hin = x;
    const int gather_blocks = (NN + 7) / 8;            // 8 warps/block
    const int gemm_blocks = (NN + 127) / 128;          // 1563

    for (int l = 0; l < 6; l++) {
        int dout = (l < 5) ? 128 : 64;
        const __nv_bfloat16* Bh = bh + (size_t)l * 49152;
        const __nv_bfloat16* Bl = bl + (size_t)l * 49152;
        const float* ga = (l < 5) ? bn_gamma + l * 128 : bn_gamma_l;
        const float* be = (l < 5) ? bn_beta  + l * 128 : bn_beta_l;
        const float* skip = (l >= 2 && l <= 4) ? outs[l - 2] : nullptr;

        gather_kernel<<<gather_blocks, 256>>>(h16, p1h, 0, 1);  // block 0 zeroes g_stats
        gather_kernel<<<gather_blocks, 256>>>(p1h, p2h, 1, 0);

        if (dout == 128)
            wmma_gemm_kernel<128><<<gemm_blocks, 512, SMEM128>>>(hin, p1h, p2h, Bh, Bl, y);
        else
            wmma_gemm_kernel<64><<<gemm_blocks, 256, SMEM64>>>(hin, p1h, p2h, Bh, Bl, y);

        bn_apply_kernel<<<4096, 256>>>(y, stats, ga, be, skip, outs[l], h16, dout);
        hin = outs[l];
    }

    seg_starts_kernel<<<(NN + 255) / 256, 256>>>(seg);
    pool_kernel<<<GG, 64>>>(hin);
    zero_launch(aggstats, 8);
    agg_stats_kernel<<<256, 256>>>();
    final_kernel<<<GG, 64>>>(aggW, aggB, agg_gamma, agg_beta, outW, outB, out);
}

// round 17
// speedup vs baseline: 1.1526x; 1.0583x over previous
#include <cuda_runtime.h>
#include <cuda_bf16.h>
#include <cuda_fp16.h>
#include <mma.h>
#include <cstdint>
#include <cstddef>

using namespace nvcuda;

#define NN 200000
#define EE 3200000
#define GG 2000
#define NBLK 196   // ceil(NN/1024)
#define WSZ (5 * 49152 + 24576)  // total W^T elements across 6 layers

// ---------------- device scratch (static, allocation-free) ----------------
__device__ int   g_cnt[NN];
__device__ int   g_off[NN + 1];
__device__ int   g_cursor[NN];
__device__ int   g_bsums[NBLK];
__device__ int   g_bscan[NBLK];
__device__ int   g_csr_src[EE];
__device__ float g_csr_norm[EE];
__device__ float g_norm[NN];
__device__ __half g_h16[(size_t)NN * 128];  // fp16 copy of current h (gather input)
__device__ __half g_p1h[(size_t)NN * 128];  // fp16 prop1
__device__ __half g_p2h[(size_t)NN * 128];  // fp16 prop2
__device__ float g_y [(size_t)NN * 128];    // GEMM output
__device__ float g_o0[(size_t)NN * 128];    // rotating layer outputs
__device__ float g_o1[(size_t)NN * 128];
__device__ float g_o2[(size_t)NN * 128];
__device__ __nv_bfloat16 g_bh[WSZ];         // W^T bf16 hi, all layers [l][n][k]
__device__ __nv_bfloat16 g_bl[WSZ];         // W^T bf16 lo
__device__ float g_stats[256];
__device__ int   g_starts[GG + 1];
__device__ float g_pool[(size_t)GG * 4 * 64];
__device__ float g_aggstats[8];
__device__ int   g_flags[2];

// ---------------- misc helpers ----------------
__device__ __forceinline__ int load_idx(const void* p, long long i, int is64) {
    if (is64) return (int)((const long long*)p)[i];
    return ((const int*)p)[i];
}

__global__ void detect_kernel(const unsigned* e, const unsigned* s) {
    if (threadIdx.x == 0 && blockIdx.x == 0) {
        int z = 1;
        for (int i = 1; i < 128; i += 2) if (e[i] != 0) { z = 0; break; }
        g_flags[0] = z;
        z = 1;
        for (int i = NN - 127; i < NN; i += 2) if (s[i] != 0) { z = 0; break; }
        g_flags[1] = z;
    }
}

__global__ void zero_kernel(float* p, long long n) {
    long long i = (long long)blockIdx.x * blockDim.x + threadIdx.x;
    long long i4 = i * 4;
    if (i4 + 3 < n) {
        *(float4*)(p + i4) = make_float4(0.f, 0.f, 0.f, 0.f);
    } else {
        for (long long j = i4; j < n; j++) p[j] = 0.f;
    }
}

// x (fp32) -> g_h16 (fp16), vectorized
__global__ void to_half_kernel(const float* __restrict__ x) {
    long long i = (long long)blockIdx.x * blockDim.x + threadIdx.x;
    long long q = i * 4;
    if (q >= (long long)NN * 128) return;
    float4 v = *(const float4*)(x + q);
    __half2 a = __floats2half2_rn(v.x, v.y);
    __half2 b = __floats2half2_rn(v.z, v.w);
    uint2 st; st.x = *(uint32_t*)&a; st.y = *(uint32_t*)&b;
    *(uint2*)(g_h16 + q) = st;
}

// ---------------- CSR build ----------------
__global__ void zero_cnt_kernel() {
    int i = blockIdx.x * blockDim.x + threadIdx.x;
    if (i < NN) g_cnt[i] = 0;
}

__global__ void hist_kernel(const void* eidx) {
    int is64 = g_flags[0];
    long long i = (long long)blockIdx.x * blockDim.x + threadIdx.x;
    if (i < EE) {
        int dst = load_idx(eidx, (long long)EE + i, is64);
        atomicAdd(&g_cnt[dst], 1);
    }
}

__global__ void scan1_kernel() {
    __shared__ int sh[1024];
    int i = blockIdx.x * 1024 + threadIdx.x;
    int v = (i < NN) ? g_cnt[i] : 0;
    sh[threadIdx.x] = v;
    __syncthreads();
    for (int o = 1; o < 1024; o <<= 1) {
        int t = (threadIdx.x >= o) ? sh[threadIdx.x - o] : 0;
        __syncthreads();
        sh[threadIdx.x] += t;
        __syncthreads();
    }
    if (i < NN) g_off[i] = sh[threadIdx.x] - v;
    if (threadIdx.x == 1023) g_bsums[blockIdx.x] = sh[1023];
}

__global__ void scan2_kernel() {
    if (threadIdx.x == 0) {
        int run = 0;
        for (int b = 0; b < NBLK; b++) { g_bscan[b] = run; run += g_bsums[b]; }
        g_off[NN] = run;
    }
}

__global__ void scan3_kernel() {
    int i = blockIdx.x * blockDim.x + threadIdx.x;
    if (i < NN) {
        int o = g_off[i] + g_bscan[i >> 10];
        g_off[i] = o;
        g_cursor[i] = o;
        float d = (float)g_cnt[i];
        g_norm[i] = (d > 0.f) ? rsqrtf(fmaxf(d, 1.0f)) : 0.f;
    }
}

__global__ void fill_kernel(const void* eidx) {
    int is64 = g_flags[0];
    long long e = (long long)blockIdx.x * blockDim.x + threadIdx.x;
    if (e < EE) {
        int src = load_idx(eidx, e, is64);
        int dst = load_idx(eidx, (long long)EE + e, is64);
        int pos = atomicAdd(&g_cursor[dst], 1);
        g_csr_src[pos] = src;
        g_csr_norm[pos] = g_norm[src];
    }
}

// ---------------- gather propagation (one warp per dst row, fp16 rows) ----------------
// sq=0: out[d] = sum h[src]*norm[src]      sq=1: sum h[src]*norm[src]^2
// zstats: block 0 additionally zeroes g_stats (BN-stats reset for this layer)
// Unroll-2 idiom (best measured across 5 variants).
__global__ void gather_kernel(const __half* __restrict__ h, __half* __restrict__ out,
                              int sq, int zstats) {
    if (zstats && blockIdx.x == 0 && threadIdx.x < 256) g_stats[threadIdx.x] = 0.f;
    int w = blockIdx.x * (blockDim.x >> 5) + (threadIdx.x >> 5);
    if (w >= NN) return;
    int lane = threadIdx.x & 31;
    int s = g_off[w], e = g_off[w + 1];
    float4 acc = make_float4(0.f, 0.f, 0.f, 0.f);
    for (int j = s; j < e; j += 32) {
        int n = min(32, e - j);
        int  idx = 0;
        float nm = 0.f;
        if (lane < n) {
            idx = g_csr_src[j + lane];
            nm  = g_csr_norm[j + lane];
            if (sq) nm *= nm;
        }
        int k = 0;
        for (; k + 1 < n; k += 2) {
            int   s0 = __shfl_sync(0xffffffffu, idx, k);
            int   s1 = __shfl_sync(0xffffffffu, idx, k + 1);
            float n0 = __shfl_sync(0xffffffffu, nm, k);
            float n1 = __shfl_sync(0xffffffffu, nm, k + 1);
            uint2 u0 = __ldg((const uint2*)(h + (size_t)s0 * 128) + lane);
            uint2 u1 = __ldg((const uint2*)(h + (size_t)s1 * 128) + lane);
            float2 a0 = __half22float2(*(__half2*)&u0.x);
            float2 b0 = __half22float2(*(__half2*)&u0.y);
            float2 a1 = __half22float2(*(__half2*)&u1.x);
            float2 b1 = __half22float2(*(__half2*)&u1.y);
            acc.x += a0.x * n0 + a1.x * n1;
            acc.y += a0.y * n0 + a1.y * n1;
            acc.z += b0.x * n0 + b1.x * n1;
            acc.w += b0.y * n0 + b1.y * n1;
        }
        if (k < n) {
            int   s0 = __shfl_sync(0xffffffffu, idx, k);
            float n0 = __shfl_sync(0xffffffffu, nm, k);
            uint2 u0 = __ldg((const uint2*)(h + (size_t)s0 * 128) + lane);
            float2 a0 = __half22float2(*(__half2*)&u0.x);
            float2 b0 = __half22float2(*(__half2*)&u0.y);
            acc.x += a0.x * n0; acc.y += a0.y * n0;
            acc.z += b0.x * n0; acc.w += b0.y * n0;
        }
    }
    __half2 o0 = __floats2half2_rn(acc.x, acc.y);
    __half2 o1 = __floats2half2_rn(acc.z, acc.w);
    uint2 st; st.x = *(uint32_t*)&o0; st.y = *(uint32_t*)&o1;
    *((uint2*)(out + (size_t)w * 128) + lane) = st;
}

// ------------- bf16 split prep for ALL weight matrices (one launch) -------------
__global__ void prep_w_all_kernel(const float* __restrict__ convW,
                                  const float* __restrict__ convWlast) {
    int idx = blockIdx.x * blockDim.x + threadIdx.x;
    if (idx >= WSZ) return;
    float v;
    if (idx < 5 * 49152) {
        int l = idx / 49152, r = idx % 49152;
        int n = r / 384, k = r % 384;
        v = convW[(size_t)l * 49152 + (size_t)k * 128 + n];
    } else {
        int r = idx - 5 * 49152;
        int n = r / 384, k = r % 384;
        v = convWlast[(size_t)k * 64 + n];
    }
    __nv_bfloat16 hi = __float2bfloat16(v);
    g_bh[idx] = hi;
    g_bl[idx] = __float2bfloat16(v - __bfloat162float(hi));
}

// ------------- WMMA bf16 GEMM (M-tile 256), fused hi/lo split + fused BN stats -------------
__device__ __forceinline__ void split4_store(__nv_bfloat16* s_ah, __nv_bfloat16* s_al, int so,
                                             float a0, float a1, float a2, float a3) {
    __nv_bfloat16 h0 = __float2bfloat16(a0), h1 = __float2bfloat16(a1);
    __nv_bfloat16 h2 = __float2bfloat16(a2), h3 = __float2bfloat16(a3);
    __nv_bfloat162 hp0; hp0.x = h0; hp0.y = h1;
    __nv_bfloat162 hp1; hp1.x = h2; hp1.y = h3;
    __nv_bfloat162 lp0, lp1;
    lp0.x = __float2bfloat16(a0 - __bfloat162float(h0));
    lp0.y = __float2bfloat16(a1 - __bfloat162float(h1));
    lp1.x = __float2bfloat16(a2 - __bfloat162float(h2));
    lp1.y = __float2bfloat16(a3 - __bfloat162float(h3));
    *(__nv_bfloat162*)(s_ah + so)     = hp0;
    *(__nv_bfloat162*)(s_ah + so + 2) = hp1;
    *(__nv_bfloat162*)(s_al + so)     = lp0;
    *(__nv_bfloat162*)(s_al + so + 2) = lp1;
}

template<int DOUT>
__global__ void __launch_bounds__(DOUT == 128 ? 512 : 256, 1)
wmma_gemm_kernel(const float* __restrict__ A0, const __half* __restrict__ A1,
                 const __half* __restrict__ A2,
                 const __nv_bfloat16* __restrict__ Bh, const __nv_bfloat16* __restrict__ Bl,
                 float* __restrict__ Y) {
    constexpr int NT  = (DOUT == 128) ? 512 : 256;   // 16 / 8 warps
    constexpr int LDS = 136;  // 128 + 8 pad
    extern __shared__ __nv_bfloat16 sm[];
    __nv_bfloat16* s_ah = sm;                        // 256  x LDS
    __nv_bfloat16* s_al = s_ah + 256 * LDS;
    __nv_bfloat16* s_bh = s_al + 256 * LDS;          // DOUT x LDS
    __nv_bfloat16* s_bl = s_bh + DOUT * LDS;

    int tid = threadIdx.x;
    int wid = tid >> 5;
    int wm = wid & 7;        // 8 m-warps; each owns m-tiles wm and wm+8 (2 x 16 rows)
    int wn = wid >> 3;       // 2 n-warps (DOUT=128) or 1 (DOUT=64)
    int row0 = blockIdx.x * 256;

    wmma::fragment<wmma::accumulator, 16, 16, 16, float> acc[2][4];
#pragma unroll
    for (int mt = 0; mt < 2; mt++)
#pragma unroll
        for (int j = 0; j < 4; j++) wmma::fill_fragment(acc[mt][j], 0.f);

#pragma unroll
    for (int kc = 0; kc < 3; kc++) {
        // Stage A chunk: 256 rows x 128 k -> hi/lo bf16 (norm folded for kc>0; zero-pad tail)
        if (kc == 0) {
            for (int q = tid; q < 256 * 32; q += NT) {
                int m = q >> 5;
                int k4 = (q & 31) * 4;
                int r = row0 + m;
                float4 v = make_float4(0.f, 0.f, 0.f, 0.f);
                if (r < NN) v = *(const float4*)(A0 + (size_t)r * 128 + k4);
                split4_store(s_ah, s_al, m * LDS + k4, v.x, v.y, v.z, v.w);
            }
        } else {
            const __half* A = (kc == 1) ? A1 : A2;
            for (int q = tid; q < 256 * 32; q += NT) {
                int m = q >> 5;
                int k4 = (q & 31) * 4;
                int r = row0 + m;
                float4 v = make_float4(0.f, 0.f, 0.f, 0.f);
                if (r < NN) {
                    float f = g_norm[r];
                    uint2 u = *(const uint2*)(A + (size_t)r * 128 + k4);
                    float2 a = __half22float2(*(__half2*)&u.x);
                    float2 b = __half22float2(*(__half2*)&u.y);
                    v = make_float4(a.x * f, a.y * f, b.x * f, b.y * f);
                }
                split4_store(s_ah, s_al, m * LDS + k4, v.x, v.y, v.z, v.w);
            }
        }
        for (int q = tid; q < DOUT * 16; q += NT) {
            int n = q >> 4;
            int k8 = (q & 15) * 8;
            size_t gi = (size_t)n * 384 + kc * 128 + k8;
            int so = n * LDS + k8;
            *(uint4*)(s_bh + so) = *(const uint4*)(Bh + gi);
            *(uint4*)(s_bl + so) = *(const uint4*)(Bl + gi);
        }
        __syncthreads();

#pragma unroll
        for (int ks = 0; ks < 8; ks++) {
            wmma::fragment<wmma::matrix_a, 16, 16, 16, __nv_bfloat16, wmma::row_major> fah[2], fal[2];
#pragma unroll
            for (int mt = 0; mt < 2; mt++) {
                int mrow = (wm + mt * 8) * 16;
                wmma::load_matrix_sync(fah[mt], s_ah + mrow * LDS + ks * 16, LDS);
                wmma::load_matrix_sync(fal[mt], s_al + mrow * LDS + ks * 16, LDS);
            }
#pragma unroll
            for (int j = 0; j < 4; j++) {
                wmma::fragment<wmma::matrix_b, 16, 16, 16, __nv_bfloat16, wmma::col_major> fbh, fbl;
                int n0 = wn * 64 + j * 16;
                wmma::load_matrix_sync(fbh, s_bh + n0 * LDS + ks * 16, LDS);
                wmma::load_matrix_sync(fbl, s_bl + n0 * LDS + ks * 16, LDS);
#pragma unroll
                for (int mt = 0; mt < 2; mt++) {
                    wmma::mma_sync(acc[mt][j], fah[mt], fbh, acc[mt][j]);
                    wmma::mma_sync(acc[mt][j], fah[mt], fbl, acc[mt][j]);
                    wmma::mma_sync(acc[mt][j], fal[mt], fbh, acc[mt][j]);
                }
            }
        }
        __syncthreads();
    }

    // Epilogue: stage result tile in smem (reuse), write Y (guarded), fused column stats
    float* s_y = (float*)sm;  // 256 x DOUT floats
#pragma unroll
    for (int mt = 0; mt < 2; mt++)
#pragma unroll
        for (int j = 0; j < 4; j++) {
            wmma::store_matrix_sync(s_y + ((wm + mt * 8) * 16) * DOUT + wn * 64 + j * 16,
                                    acc[mt][j], DOUT, wmma::mem_row_major);
        }
    __syncthreads();
    for (int q = tid; q < 256 * (DOUT / 4); q += NT) {
        int r = q / (DOUT / 4);
        int c4 = (q % (DOUT / 4)) * 4;
        if (row0 + r < NN)
            *(float4*)(Y + (size_t)(row0 + r) * DOUT + c4) = *(float4*)(s_y + r * DOUT + c4);
    }
    {
        // NT/DOUT = 4 row-groups of 64 rows each; padded rows are exact zeros -> stats safe
        int col = tid % DOUT;
        int hh = tid / DOUT;   // 0..3
        float s = 0.f, ss = 0.f;
        for (int r = hh * 64; r < hh * 64 + 64; r++) {
            float v = s_y[r * DOUT + col];
            s += v; ss += v * v;
        }
        atomicAdd(&g_stats[col], s);
        atomicAdd(&g_stats[DOUT + col], ss);
    }
}

// ------------- BN apply (+ReLU +skip, writes fp32 out and fp16 copy) -------------
__global__ void bn_apply_kernel(const float* __restrict__ y, const float* __restrict__ stats,
                                const float* __restrict__ gamma, const float* __restrict__ beta,
                                const float* __restrict__ skip, float* __restrict__ out,
                                __half* __restrict__ out16, int d) {
    __shared__ float sc[128], sh[128];
    if (threadIdx.x < d) {
        float m = stats[threadIdx.x] / (float)NN;
        float v = stats[d + threadIdx.x] / (float)NN - m * m;
        float inv = rsqrtf(v + 1e-5f);
        float gi = gamma[threadIdx.x] * inv;
        sc[threadIdx.x] = gi;
        sh[threadIdx.x] = beta[threadIdx.x] - m * gi;
    }
    __syncthreads();
    long long total = (long long)NN * d / 2;
    long long stride = (long long)gridDim.x * blockDim.x;
    for (long long t = (long long)blockIdx.x * blockDim.x + threadIdx.x; t < total; t += stride) {
        long long i = t * 2;
        int f = (int)(i & (d - 1));
        float2 yv = *(const float2*)(y + i);
        float v0 = yv.x * sc[f] + sh[f];
        float v1 = yv.y * sc[f + 1] + sh[f + 1];
        v0 = fmaxf(v0, 0.f); v1 = fmaxf(v1, 0.f);
        if (skip) {
            float2 sv = *(const float2*)(skip + i);
            v0 += sv.x; v1 += sv.y;
        }
        *(float2*)(out + i) = make_float2(v0, v1);
        __half2 hv = __floats2half2_rn(v0, v1);
        *(__half2*)(out16 + i) = hv;
    }
}

// ------------- pooling / head -------------
__global__ void seg_starts_kernel(const void* seg) {
    int is64 = g_flags[1];
    long long i = (long long)blockIdx.x * blockDim.x + threadIdx.x;
    if (i >= NN) return;
    int s = load_idx(seg, i, is64);
    if (i == 0) {
        for (int g = 0; g <= s; g++) g_starts[g] = 0;
    } else {
        int sp = load_idx(seg, i - 1, is64);
        for (int g = sp + 1; g <= s; g++) g_starts[g] = (int)i;
    }
    if (i == NN - 1) {
        for (int g = s + 1; g <= GG; g++) g_starts[g] = NN;
    }
}

__global__ void pool_kernel(const float* __restrict__ h) {
    int g = blockIdx.x, f = threadIdx.x;
    int s = g_starts[g], e = g_starts[g + 1];
    float mx = -3.4e38f, mn = 3.4e38f, sum = 0.f, ssq = 0.f;
    for (int n = s; n < e; n++) {
        float v = h[(size_t)n * 64 + f];
        mx = fmaxf(mx, v); mn = fminf(mn, v);
        sum += v; ssq += v * v;
    }
    float c = (float)(e - s);
    float mean = sum / fmaxf(c, 1.f);
    float var = (ssq - c * mean * mean) / fmaxf(c - 1.f, 1.f);
    float sd = sqrtf(fmaxf(var, 0.f));
    float* P = g_pool + (size_t)g * 256;
    P[f] = mx; P[64 + f] = mn; P[128 + f] = mean; P[192 + f] = sd;
}

__global__ void agg_stats_kernel() {
    __shared__ float loc[8];
    if (threadIdx.x < 8) loc[threadIdx.x] = 0.f;
    __syncthreads();
    float s0 = 0, s1 = 0, s2 = 0, s3 = 0, q0 = 0, q1 = 0, q2 = 0, q3 = 0;
    long long total = (long long)GG * 256;
    long long stride = (long long)gridDim.x * blockDim.x;
    for (long long i = (long long)blockIdx.x * blockDim.x + threadIdx.x; i < total; i += stride) {
        int c = (int)((i >> 6) & 3);
        float v = g_pool[i];
        if (c == 0)      { s0 += v; q0 += v * v; }
        else if (c == 1) { s1 += v; q1 += v * v; }
        else if (c == 2) { s2 += v; q2 += v * v; }
        else             { s3 += v; q3 += v * v; }
    }
    atomicAdd(&loc[0], s0); atomicAdd(&loc[4], q0);
    atomicAdd(&loc[1], s1); atomicAdd(&loc[5], q1);
    atomicAdd(&loc[2], s2); atomicAdd(&loc[6], q2);
    atomicAdd(&loc[3], s3); atomicAdd(&loc[7], q3);
    __syncthreads();
    if (threadIdx.x < 8) atomicAdd(&g_aggstats[threadIdx.x], loc[threadIdx.x]);
}

__global__ void final_kernel(const float* __restrict__ aggW, const float* __restrict__ aggB,
                             const float* __restrict__ agg_gamma, const float* __restrict__ agg_beta,
                             const float* __restrict__ outW, const float* __restrict__ outB,
                             float* __restrict__ out) {
    __shared__ float flat[256];
    __shared__ float red[2];
    int g = blockIdx.x, t = threadIdx.x;
    float cnt = (float)GG * 64.f;
#pragma unroll
    for (int c = 0; c < 4; c++) {
        float m = g_aggstats[c] / cnt;
        float v = g_aggstats[4 + c] / cnt - m * m;
        float inv = rsqrtf(v + 1e-5f);
        float x = g_pool[(size_t)g * 256 + c * 64 + t];
        flat[c * 64 + t] = (x - m) * inv * agg_gamma[c] + agg_beta[c];
    }
    __syncthreads();
    float hg = aggB[t];
#pragma unroll 8
    for (int j = 0; j < 256; j++) hg += flat[j] * aggW[t * 256 + j];
    float val = hg * outW[t];
#pragma unroll
    for (int o = 16; o > 0; o >>= 1) val += __shfl_down_sync(0xffffffff, val, o);
    if ((t & 31) == 0) red[t >> 5] = val;
    __syncthreads();
    if (t == 0) out[g] = red[0] + red[1] + outB[0];
}

// ---------------- host ----------------
static inline void zero_launch(float* p, long long n) {
    long long n4 = (n + 3) / 4;
    int blocks = (int)((n4 + 255) / 256);
    zero_kernel<<<blocks, 256>>>(p, n);
}

extern "C" void kernel_launch(void* const* d_in, const int* in_sizes, int n_in,
                              void* d_out, int out_size) {
    const float* x            = (const float*)d_in[0];
    const void*  eidx         = d_in[1];
    const void*  seg          = d_in[2];
    const float* conv_W       = (const float*)d_in[3];
    const float* conv_W_last  = (const float*)d_in[4];
    const float* bn_gamma     = (const float*)d_in[5];
    const float* bn_beta      = (const float*)d_in[6];
    const float* bn_gamma_l   = (const float*)d_in[7];
    const float* bn_beta_l    = (const float*)d_in[8];
    const float* agg_gamma    = (const float*)d_in[9];
    const float* agg_beta     = (const float*)d_in[10];
    const float* aggW         = (const float*)d_in[11];
    const float* aggB         = (const float*)d_in[12];
    const float* outW         = (const float*)d_in[13];
    const float* outB         = (const float*)d_in[14];
    float* out = (float*)d_out;

    float *y, *o0, *o1, *o2, *stats, *aggstats;
    __half *h16, *p1h, *p2h;
    __nv_bfloat16 *bh, *bl;
    cudaGetSymbolAddress((void**)&y, g_y);
    cudaGetSymbolAddress((void**)&o0, g_o0);
    cudaGetSymbolAddress((void**)&o1, g_o1);
    cudaGetSymbolAddress((void**)&o2, g_o2);
    cudaGetSymbolAddress((void**)&stats, g_stats);
    cudaGetSymbolAddress((void**)&aggstats, g_aggstats);
    cudaGetSymbolAddress((void**)&h16, g_h16);
    cudaGetSymbolAddress((void**)&p1h, g_p1h);
    cudaGetSymbolAddress((void**)&p2h, g_p2h);
    cudaGetSymbolAddress((void**)&bh, g_bh);
    cudaGetSymbolAddress((void**)&bl, g_bl);

    // smem: A(256 rows hi+lo) + B(DOUT rows hi+lo), LDS=136 bf16
    const int SMEM128 = (256 * 2 + 128 * 2) * 136 * 2;  // 208896
    const int SMEM64  = (256 * 2 +  64 * 2) * 136 * 2;  // 174080
    cudaFuncSetAttribute(wmma_gemm_kernel<128>,
                         cudaFuncAttributeMaxDynamicSharedMemorySize, SMEM128);
    cudaFuncSetAttribute(wmma_gemm_kernel<64>,
                         cudaFuncAttributeMaxDynamicSharedMemorySize, SMEM64);

    detect_kernel<<<1, 32>>>((const unsigned*)eidx, (const unsigned*)seg);

    // ---- CSR build (by dst) + all-layer weight prep (off the layer chain) ----
    zero_cnt_kernel<<<(NN + 255) / 256, 256>>>();
    hist_kernel<<<(EE + 255) / 256, 256>>>(eidx);
    scan1_kernel<<<NBLK, 1024>>>();
    scan2_kernel<<<1, 32>>>();
    scan3_kernel<<<(NN + 255) / 256, 256>>>();
    fill_kernel<<<(EE + 255) / 256, 256>>>(eidx);
    prep_w_all_kernel<<<(WSZ + 255) / 256, 256>>>(conv_W, conv_W_last);

    // fp16 copy of x
    to_half_kernel<<<(int)(((long long)NN * 128 / 4 + 255) / 256), 256>>>(x);

    float* outs[6] = {o0, o1, o2, o0, o1, o2};
    const float* hin = x;
    const int gather_blocks = (NN + 7) / 8;            // 8 warps/block
    const int gemm_blocks = (NN + 255) / 256;          // 782

    for (int l = 0; l < 6; l++) {
        int dout = (l < 5) ? 128 : 64;
        const __nv_bfloat16* Bh = bh + (size_t)l * 49152;
        const __nv_bfloat16* Bl = bl + (size_t)l * 49152;
        const float* ga = (l < 5) ? bn_gamma + l * 128 : bn_gamma_l;
        const float* be = (l < 5) ? bn_beta  + l * 128 : bn_beta_l;
        const float* skip = (l >= 2 && l <= 4) ? outs[l - 2] : nullptr;

        gather_kernel<<<gather_blocks, 256>>>(h16, p1h, 0, 1);  // block 0 zeroes g_stats
        gather_kernel<<<gather_blocks, 256>>>(p1h, p2h, 1, 0);

        if (dout == 128)
            wmma_gemm_kernel<128><<<gemm_blocks, 512, SMEM128>>>(hin, p1h, p2h, Bh, Bl, y);
        else
            wmma_gemm_kernel<64><<<gemm_blocks, 256, SMEM64>>>(hin, p1h, p2h, Bh, Bl, y);

        bn_apply_kernel<<<4096, 256>>>(y, stats, ga, be, skip, outs[l], h16, dout);
        hin = outs[l];
    }

    seg_starts_kernel<<<(NN + 255) / 256, 256>>>(seg);
    pool_kernel<<<GG, 64>>>(hin);
    zero_launch(aggstats, 8);
    agg_stats_kernel<<<256, 256>>>();
    final_kernel<<<GG, 64>>>(aggW, aggB, agg_gamma, agg_beta, outW, outB, out);
}